// round 13
// baseline (speedup 1.0000x reference)
#include <cuda_runtime.h>

#define BATCH 16
#define D 128
#define NN 16
#define E 120
#define OUTB (256 * 256)
#define GRID 256

// Scratch: partial P sums per 16-row d-chunk.
__device__ float g_Pp1[BATCH][8][256];
__device__ float g_Pp2[BATCH][8][256];
__device__ int   g_cnt_a[BATCH];   // per-batch arrive counters
__device__ int   g_cnt_b[BATCH];   // per-batch depart counters (reset)

// ---------------------------------------------------------------------------
// Single kernel, per-batch sync, sparse output fixup:
//   step 1: write this block's 16 output rows as ZEROS (no dependencies;
//           4MB chip-wide DRAM drain overlaps everything that follows)
//   Phase A: block (b,m,chunk) computes P partials (front-batched loads)
//   pre-spin: diagonal stores, compacted edge-pair lists
//   Phase B: reduce partials, scatter-store only the ~1% nonzero entries
// ---------------------------------------------------------------------------
__global__ void __launch_bounds__(256, 4)
kFused(const float* __restrict__ Fs,
       const float* __restrict__ Ft,
       const float* __restrict__ Us,
       const float* __restrict__ Ut,
       const int* __restrict__ As,
       const int* __restrict__ At,
       const float* __restrict__ lam1,
       const float* __restrict__ lam2,
       float* __restrict__ out) {
    __shared__ float Fts[D * NN];     // [d'][j]
    __shared__ float ws[16][132];     // padded: conflict-free float4 reads
    __shared__ float Fss[16][17];     // [dloc][i]
    __shared__ float tmps[16][17];    // [dloc][j]
    __shared__ float P1s[256];
    __shared__ float P2s[256];
    __shared__ int   boths[E];
    __shared__ int   pairs1[E];       // packed (i1p<<4)|i1q, both-valid pairs
    __shared__ int   valid2[16];      // i2q > i2p with both[e2]
    __shared__ int   n1, n2;

    const int t   = threadIdx.x;
    const int b   = blockIdx.x >> 4;
    const int m   = (blockIdx.x >> 3) & 1;
    const int c0  = (blockIdx.x & 7) * 16;
    const int i2p = blockIdx.x & 15;           // output-row / phase-B role

    if (t == 0) { n1 = 0; n2 = 0; }

    // ========== 1. zero-write own 16 rows immediately ==========
    {
        const float4 z = make_float4(0.f, 0.f, 0.f, 0.f);
        float* orow = out + b * OUTB + (i2p * 16 + (t >> 4)) * 256;
        const int tq = t & 15;
#pragma unroll
        for (int s = 0; s < 4; s++)
            *reinterpret_cast<float4*>(orow + s * 64 + tq * 4) = z;
    }

    // ========== 2. front-batched global loads ==========
    const float* lam = m ? lam2 : lam1;
    const float* ft  = Ft + b * D * NN;
    const float* fs  = Fs + b * D * NN;

    const float4* ft4  = reinterpret_cast<const float4*>(ft);
    const float4* lam4 = reinterpret_cast<const float4*>(lam + c0 * D);

    const float4 rf0 = ft4[t];
    const float4 rf1 = ft4[t + 256];
    const float4 rw0 = lam4[t];
    const float4 rw1 = lam4[t + 256];
    const float  rfs = fs[c0 * NN + t];
    float r2[8];
    {
        const int d  = t & 15;
        const int dp = t >> 4;
#pragma unroll
        for (int k = 0; k < 8; k++)
            r2[k] = lam[(dp + 16 * k) * D + c0 + d];
    }
    int ea = 0;
    if (t < E)
        ea = (As[b * E + t] > 0) && (At[b * E + t] > 0);
    float mpv = 0.f;
    if (t < 16) {
#pragma unroll
        for (int d = 0; d < NN; d++)
            mpv += Us[b * 256 + d * 16 + i2p] * Ut[b * 256 + d * 16 + t];
    }

    // stash into smem
    *reinterpret_cast<float4*>(&Fts[4 * t])         = rf0;
    *reinterpret_cast<float4*>(&Fts[4 * (t + 256)]) = rf1;
    {
        const int e0 = 4 * t;
        ws[e0 >> 7][e0 & 127]       = rw0.x;
        ws[e0 >> 7][(e0 & 127) + 1] = rw0.y;
        ws[e0 >> 7][(e0 & 127) + 2] = rw0.z;
        ws[e0 >> 7][(e0 & 127) + 3] = rw0.w;
        const int e1 = 4 * (t + 256);
        ws[e1 >> 7][e1 & 127]       = rw1.x;
        ws[e1 >> 7][(e1 & 127) + 1] = rw1.y;
        ws[e1 >> 7][(e1 & 127) + 2] = rw1.z;
        ws[e1 >> 7][(e1 & 127) + 3] = rw1.w;
    }
    Fss[t >> 4][t & 15] = rfs;
    if (t < E) boths[t] = ea;
    __syncthreads();

    // pass-2 fixup: ws = relu(ws + lam^T term)
    {
        const int d  = t & 15;
        const int dp = t >> 4;
#pragma unroll
        for (int k = 0; k < 8; k++) {
            const float v = ws[d][dp + 16 * k] + r2[k];
            ws[d][dp + 16 * k] = v > 0.f ? v : 0.f;
        }
    }
    __syncthreads();

    // ========== 3. GEMM1: tmp[dloc][j] = ws[dloc][:] . Fts[:][j] ==========
    {
        const int j    = t & 15;
        const int dloc = t >> 4;
        const float4* wv = reinterpret_cast<const float4*>(ws[dloc]);

        float a0 = 0.f, a1 = 0.f;
#pragma unroll
        for (int q = 0; q < D / 8; q++) {
            const float4 wa = wv[2 * q];
            const float4 wb = wv[2 * q + 1];
            const int base = 8 * q * NN + j;
            a0 += wa.x * Fts[base + 0 * NN] + wa.y * Fts[base + 1 * NN]
                + wa.z * Fts[base + 2 * NN] + wa.w * Fts[base + 3 * NN];
            a1 += wb.x * Fts[base + 4 * NN] + wb.y * Fts[base + 5 * NN]
                + wb.z * Fts[base + 6 * NN] + wb.w * Fts[base + 7 * NN];
        }
        tmps[dloc][j] = a0 + a1;
    }
    __syncthreads();

    // GEMM2: Pp[i][jj] = sum_d Fss[d][i] * tmps[d][jj] -> publish
    {
        const int i  = t >> 4;
        const int jj = t & 15;
        float p = 0.f;
#pragma unroll
        for (int d = 0; d < 16; d++)
            p += Fss[d][i] * tmps[d][jj];

        float* pp = m ? &g_Pp2[b][blockIdx.x & 7][0]
                      : &g_Pp1[b][blockIdx.x & 7][0];
        pp[t] = p;
    }
    __syncthreads();

    if (t == 0) {
        __threadfence();
        atomicAdd(&g_cnt_a[b], 1);
    }

    // ========== 4. overlapped with other blocks finishing ==========
    // diagonal stores (only nonzero entries independent of P)
    if (t < 16)
        out[b * OUTB + (i2p * 16 + t) * 257] = mpv;

    // compacted (i1p,i1q) pair list over all both-valid edges
    // invert e -> (r,c): row k's first edge is e = k*(31-k)/2
    if (t < E && ea) {
        int r = 0;
#pragma unroll
        for (int k = 1; k < 15; k++)
            if (t >= k * (31 - k) / 2) r = k;
        const int c = t - r * (29 - r) / 2 + 1;
        pairs1[atomicAdd(&n1, 1)] = (r << 4) | c;
    }
    // valid i2q list for this block's i2p
    if (t > i2p && t < 16) {
        const int e2 = i2p * (29 - i2p) / 2 + t - 1;
        if (boths[e2]) valid2[atomicAdd(&n2, 1)] = t;
    }

    // ========== 5. per-batch wait ==========
    if (t == 0) {
        volatile int* ca = &g_cnt_a[b];
        while (*ca < 16) __nanosleep(32);
        __threadfence();
        const int rb = atomicAdd(&g_cnt_b[b], 1);
        if (rb == 15) {
            atomicExch(&g_cnt_a[b], 0);
            atomicExch(&g_cnt_b[b], 0);
        }
    }
    __syncthreads();

    // ========== 6. reduce partials, sparse fixup stores ==========
    {
        float s1 = 0.f, s2 = 0.f;
#pragma unroll
        for (int c = 0; c < 8; c++) {
            s1 += g_Pp1[b][c][t];
            s2 += g_Pp2[b][c][t];
        }
        P1s[t] = s1;
        P2s[t] = s2;
    }
    __syncthreads();

    {
        const int nn1 = n1;
        const int nn2 = n2;
        float* ob = out + b * OUTB;
        for (int w2 = 0; w2 < nn2; w2++) {
            const int i2q = valid2[w2];
            for (int idx = t; idx < nn1; idx += 256) {
                const int pk  = pairs1[idx];
                const int a   = pk >> 4;     // i1p
                const int c   = pk & 15;     // i1q
                const float val = P1s[i2p * 16 + a] + P2s[i2p * 16 + c]
                                + P2s[i2q * 16 + a] + P1s[i2q * 16 + c];
                ob[(i2p * 16 + a) * 256 + i2q * 16 + c] = val;
            }
        }
    }
}

extern "C" void kernel_launch(void* const* d_in, const int* in_sizes, int n_in,
                              void* d_out, int out_size) {
    const int*   As   = (const int*)d_in[0];
    const int*   At   = (const int*)d_in[1];
    const float* Fs   = (const float*)d_in[2];
    const float* Ft   = (const float*)d_in[3];
    const float* Us   = (const float*)d_in[4];
    const float* Ut   = (const float*)d_in[5];
    const float* lam1 = (const float*)d_in[6];
    const float* lam2 = (const float*)d_in[7];
    float* out = (float*)d_out;

    kFused<<<GRID, 256>>>(Fs, Ft, Us, Ut, As, At, lam1, lam2, out);
}